// round 13
// baseline (speedup 1.0000x reference)
#include <cuda_runtime.h>
#include <cstdint>

// AFM forward: 2 samples per CTA, 2 pairs x 2 samples per thread.
// Hidden GEMV via fma.rn.f32x2 with SAMPLE-packed streams:
//   inner products packed {s0,s1} once; W/bias/fcw duplicated {v,v} in smem.
// -> zero packs inside the MLP loop.
// cross term = (sum_p e^{s_p} g_p) / (sum_p e^{s_p}),  g_p = inner_p . fc_w

#define NF 24
#define NE 16
#define NA 32
#define NP 276            // 24*23/2
#define NS 2              // samples per block
#define HPT 138           // thread t handles pairs t and t+HPT
#define NTHREADS 160      // 5 warps
#define NWARP 5
#define EPAD 20           // padded row length for s_emb (80B)

typedef unsigned long long u64;

__device__ __forceinline__ u64 pack2(float lo, float hi) {
    u64 r;
    asm("mov.b64 %0, {%1, %2};" : "=l"(r) : "f"(lo), "f"(hi));
    return r;
}
__device__ __forceinline__ void unpack2(u64 v, float& lo, float& hi) {
    asm("mov.b64 {%0, %1}, %2;" : "=f"(lo), "=f"(hi) : "l"(v));
}
__device__ __forceinline__ u64 fma2(u64 a, u64 b, u64 c) {
    u64 d;
    asm("fma.rn.f32x2 %0, %1, %2, %3;" : "=l"(d) : "l"(a), "l"(b), "l"(c));
    return d;
}

__global__ __launch_bounds__(NTHREADS, 3) void afm_kernel(
    const int* __restrict__ x_raw,            // [B,24] int32 OR int64 (auto-detect)
    const float* __restrict__ embed_table,    // [V,16]
    const float* __restrict__ linear_table,   // [V,1]
    const float* __restrict__ linear_bias,    // [1]
    const float* __restrict__ attn_W,         // [16,32]
    const float* __restrict__ attn_b,         // [32]
    const float* __restrict__ proj_w,         // [32,1]
    const float* __restrict__ proj_b,         // [1]
    const float* __restrict__ fc_w,           // [16,1]
    const float* __restrict__ fc_b,           // [1]
    float* __restrict__ out)                  // [B,1]
{
    __shared__ __align__(16) float s_emb[NS][NF][EPAD];
    __shared__ __align__(16) u64   s_W2[NE][NA];    // {w,w} duplicated, 4 KB
    __shared__ __align__(16) u64   s_b2[NA];        // {b,b}
    __shared__ __align__(16) u64   s_fcw2[NE];      // {f,f}
    __shared__ __align__(16) float s_projw[NA];
    __shared__ int   s_gid[NS][NF];
    __shared__ float s_lin[NS][NF];
    __shared__ float s_scal[2];
    __shared__ float red_max[NS][NWARP];
    __shared__ float red_se[NS][NWARP];
    __shared__ float red_sg[NS][NWARP];
    __shared__ float s_smax[NS];

    const int tid  = threadIdx.x;
    const int wid  = tid >> 5;
    const int lane = tid & 31;
    const long long b0 = (long long)blockIdx.x * NS;

    // dtype probe: int64 values < 50000 have zero high words at odd positions.
    const bool is64 = (x_raw[1] == 0) & (x_raw[3] == 0) & (x_raw[5] == 0) & (x_raw[7] == 0);

    // ---- stage indices + linear terms ----
    if (tid < NS * NF) {
        int s = tid / NF;
        int f = tid - s * NF;
        long long flat = (b0 + s) * NF + f;
        int xv = is64 ? x_raw[flat * 2] : x_raw[flat];
        int gid = xv + f * 50000;
        s_gid[s][f] = gid;
        s_lin[s][f] = linear_table[gid];
    }
    for (int t = tid; t < NE * NA; t += NTHREADS) {
        float w = attn_W[t];
        ((u64*)s_W2)[t] = pack2(w, w);
    }
    if (tid < NA) {
        float b = attn_b[tid];
        s_b2[tid] = pack2(b, b);
        s_projw[tid] = proj_w[tid];
    }
    if (tid < NE) {
        float f = fc_w[tid];
        s_fcw2[tid] = pack2(f, f);
    }
    if (tid == 0) {
        s_scal[0] = proj_b[0];
        s_scal[1] = fc_b[0] + linear_bias[0];
    }
    __syncthreads();

    // ---- gather embeddings as float4 ----
    for (int t = tid; t < NS * NF * 4; t += NTHREADS) {
        int s = t / (NF * 4);
        int rem = t - s * (NF * 4);
        int f = rem >> 2, q = rem & 3;
        const float4* src = (const float4*)embed_table;
        ((float4*)&s_emb[s][f][0])[q] = src[(long long)s_gid[s][f] * 4 + q];
    }
    __syncthreads();

    // ---- per-thread: pairs A=tid, B=tid+HPT, samples packed {s0,s1} ----
    const bool active = (tid < HPT);
    float scA0 = -1e30f, scA1 = -1e30f, scB0 = -1e30f, scB1 = -1e30f;
    float gA0 = 0.f, gA1 = 0.f, gB0 = 0.f, gB1 = 0.f;

    if (active) {
        // decode both pairs
        int pA = tid, rA = 0, baseA = 0;
        while (pA >= baseA + (NF - 1 - rA)) { baseA += NF - 1 - rA; rA++; }
        int cA = rA + 1 + (pA - baseA);
        int pB = tid + HPT, rB = 0, baseB = 0;
        while (pB >= baseB + (NF - 1 - rB)) { baseB += NF - 1 - rB; rB++; }
        int cB = rB + 1 + (pB - baseB);

        // inner products, packed per element as {sample0, sample1}
        u64 inA[NE], inB[NE];
        #pragma unroll
        for (int q = 0; q < 4; q++) {
            float4 a0 = ((const float4*)&s_emb[0][rA][0])[q];
            float4 c0 = ((const float4*)&s_emb[0][cA][0])[q];
            float4 a1 = ((const float4*)&s_emb[1][rA][0])[q];
            float4 c1 = ((const float4*)&s_emb[1][cA][0])[q];
            inA[q*4+0] = pack2(a0.x*c0.x, a1.x*c1.x);
            inA[q*4+1] = pack2(a0.y*c0.y, a1.y*c1.y);
            inA[q*4+2] = pack2(a0.z*c0.z, a1.z*c1.z);
            inA[q*4+3] = pack2(a0.w*c0.w, a1.w*c1.w);
            float4 b0v = ((const float4*)&s_emb[0][rB][0])[q];
            float4 d0 = ((const float4*)&s_emb[0][cB][0])[q];
            float4 b1v = ((const float4*)&s_emb[1][rB][0])[q];
            float4 d1 = ((const float4*)&s_emb[1][cB][0])[q];
            inB[q*4+0] = pack2(b0v.x*d0.x, b1v.x*d1.x);
            inB[q*4+1] = pack2(b0v.y*d0.y, b1v.y*d1.y);
            inB[q*4+2] = pack2(b0v.z*d0.z, b1v.z*d1.z);
            inB[q*4+3] = pack2(b0v.w*d0.w, b1v.w*d1.w);
        }

        // g = inner . fc_w, packed over samples
        u64 gA01 = 0ULL, gB01 = 0ULL;  // {0.f, 0.f}
        #pragma unroll
        for (int e = 0; e < NE; e++) {
            u64 fw = s_fcw2[e];
            gA01 = fma2(inA[e], fw, gA01);
            gB01 = fma2(inB[e], fw, gB01);
        }
        unpack2(gA01, gA0, gA1);
        unpack2(gB01, gB0, gB1);

        // h = relu(inner @ W + b); s = h . proj_w + proj_b
        // 4 chunks of 8 cols; accumulators hold {sample0, sample1} per col.
        // Zero packs inside: multipliers are preloaded packed inner values,
        // multiplicands come from the duplicated s_W2 table.
        float sA0 = s_scal[0], sA1 = s_scal[0], sB0 = s_scal[0], sB1 = s_scal[0];
        #pragma unroll
        for (int ch = 0; ch < 4; ch++) {
            u64 hA[8], hB[8];
            #pragma unroll
            for (int j = 0; j < 8; j++) {
                u64 bj = s_b2[ch*8 + j];
                hA[j] = bj; hB[j] = bj;
            }

            #pragma unroll
            for (int e = 0; e < NE; e++) {
                const ulonglong2* wr = (const ulonglong2*)&s_W2[e][ch*8];
                ulonglong2 w01 = wr[0];
                ulonglong2 w23 = wr[1];
                ulonglong2 w45 = wr[2];
                ulonglong2 w67 = wr[3];
                u64 iA = inA[e], iB = inB[e];
                hA[0] = fma2(iA, w01.x, hA[0]);  hB[0] = fma2(iB, w01.x, hB[0]);
                hA[1] = fma2(iA, w01.y, hA[1]);  hB[1] = fma2(iB, w01.y, hB[1]);
                hA[2] = fma2(iA, w23.x, hA[2]);  hB[2] = fma2(iB, w23.x, hB[2]);
                hA[3] = fma2(iA, w23.y, hA[3]);  hB[3] = fma2(iB, w23.y, hB[3]);
                hA[4] = fma2(iA, w45.x, hA[4]);  hB[4] = fma2(iB, w45.x, hB[4]);
                hA[5] = fma2(iA, w45.y, hA[5]);  hB[5] = fma2(iB, w45.y, hB[5]);
                hA[6] = fma2(iA, w67.x, hA[6]);  hB[6] = fma2(iB, w67.x, hB[6]);
                hA[7] = fma2(iA, w67.y, hA[7]);  hB[7] = fma2(iB, w67.y, hB[7]);
            }

            #pragma unroll
            for (int j = 0; j < 8; j++) {
                float pj = s_projw[ch*8 + j];
                float lo, hi;
                unpack2(hA[j], lo, hi);
                sA0 = fmaf(fmaxf(lo,0.f), pj, sA0);
                sA1 = fmaf(fmaxf(hi,0.f), pj, sA1);
                unpack2(hB[j], lo, hi);
                sB0 = fmaf(fmaxf(lo,0.f), pj, sB0);
                sB1 = fmaf(fmaxf(hi,0.f), pj, sB1);
            }
        }
        scA0 = sA0; scA1 = sA1; scB0 = sB0; scB1 = sB1;
    }

    // ---- block softmax-max reduction (both samples) ----
    float m0 = fmaxf(scA0, scB0);
    float m1 = fmaxf(scA1, scB1);
    #pragma unroll
    for (int o = 16; o > 0; o >>= 1) {
        m0 = fmaxf(m0, __shfl_xor_sync(0xffffffffu, m0, o));
        m1 = fmaxf(m1, __shfl_xor_sync(0xffffffffu, m1, o));
    }
    if (lane == 0) { red_max[0][wid] = m0; red_max[1][wid] = m1; }
    __syncthreads();
    if (tid == 0) {
        float a = red_max[0][0], b = red_max[1][0];
        #pragma unroll
        for (int w = 1; w < NWARP; w++) {
            a = fmaxf(a, red_max[0][w]);
            b = fmaxf(b, red_max[1][w]);
        }
        s_smax[0] = a; s_smax[1] = b;
    }
    __syncthreads();

    // ---- exp + weighted sums ----
    const float smax0 = s_smax[0], smax1 = s_smax[1];
    float exA0 = active ? __expf(scA0 - smax0) : 0.f;
    float exA1 = active ? __expf(scA1 - smax1) : 0.f;
    float exB0 = active ? __expf(scB0 - smax0) : 0.f;
    float exB1 = active ? __expf(scB1 - smax1) : 0.f;
    float se0 = exA0 + exB0;
    float se1 = exA1 + exB1;
    float sg0 = exA0 * gA0 + exB0 * gB0;
    float sg1 = exA1 * gA1 + exB1 * gB1;
    #pragma unroll
    for (int o = 16; o > 0; o >>= 1) {
        se0 += __shfl_xor_sync(0xffffffffu, se0, o);
        sg0 += __shfl_xor_sync(0xffffffffu, sg0, o);
        se1 += __shfl_xor_sync(0xffffffffu, se1, o);
        sg1 += __shfl_xor_sync(0xffffffffu, sg1, o);
    }
    if (lane == 0) {
        red_se[0][wid] = se0; red_sg[0][wid] = sg0;
        red_se[1][wid] = se1; red_sg[1][wid] = sg1;
    }
    __syncthreads();

    if (tid < NS) {
        int s = tid;
        float tse = 0.f, tsg = 0.f;
        #pragma unroll
        for (int w = 0; w < NWARP; w++) { tse += red_se[s][w]; tsg += red_sg[s][w]; }
        float lin = 0.f;
        #pragma unroll
        for (int f = 0; f < NF; f++) lin += s_lin[s][f];
        out[b0 + s] = lin + s_scal[1] + tsg / tse;
    }
}

extern "C" void kernel_launch(void* const* d_in, const int* in_sizes, int n_in,
                              void* d_out, int out_size) {
    const int* x              = (const int*)d_in[0];
    const float* embed_table  = (const float*)d_in[1];
    const float* linear_table = (const float*)d_in[2];
    const float* linear_bias  = (const float*)d_in[3];
    const float* attn_W       = (const float*)d_in[4];
    const float* attn_b       = (const float*)d_in[5];
    const float* proj_w       = (const float*)d_in[6];
    const float* proj_b       = (const float*)d_in[7];
    const float* fc_w         = (const float*)d_in[8];
    const float* fc_b         = (const float*)d_in[9];
    float* out = (float*)d_out;

    int B = out_size;                 // one output per sample
    int nblocks = (B + NS - 1) / NS;  // 16384 -> 8192
    afm_kernel<<<nblocks, NTHREADS>>>(x, embed_table, linear_table, linear_bias,
                                      attn_W, attn_b, proj_w, proj_b, fc_w, fc_b, out);
}

// round 14
// speedup vs baseline: 1.8598x; 1.8598x over previous
#include <cuda_runtime.h>
#include <cuda_bf16.h>
#include <cstdint>

// AFM forward, tensor-core formulation.
// Per CTA: 2 samples. Inner[576(pad),16] built in-register as bf16 MMA A-frags;
// W' = [attn_W | fc_w | 0pad] as [16,40]; D = Inner @ W' via mma.sync.m16n8k16
// (5 n-tiles). Epilogue on D frags: h=relu(d+b), score=h.projw+proj_b, g=col32.
// Then block softmax over 276 pairs per sample.
// cross term = (sum_p e^{s_p} g_p) / (sum_p e^{s_p})

#define NF 24
#define NE 16
#define NA 32
#define NP 276
#define NS 2
#define PPS 288            // padded pairs per sample (18 tiles of 16)
#define ROWS (NS*PPS)      // 576
#define NTILES (ROWS/16)   // 36
#define NWARP 4
#define NTHREADS 128
#define TPW (NTILES/NWARP) // 9 tiles per warp
#define EPAD 18            // padded emb row (72B, float2-aligned)
#define NWT 40             // W' cols: 32 W + 1 fcw + 7 zero

// pack two f32 -> bf16x2 (lo = first arg)
__device__ __forceinline__ uint32_t bf16x2_of(float lo, float hi) {
    uint32_t d;
    asm("cvt.rn.bf16x2.f32 %0, %1, %2;" : "=r"(d) : "f"(hi), "f"(lo));
    return d;
}

__device__ __forceinline__ void mma_bf16(float d[4],
    uint32_t a0, uint32_t a1, uint32_t a2, uint32_t a3,
    uint32_t b0, uint32_t b1)
{
    asm volatile(
        "mma.sync.aligned.m16n8k16.row.col.f32.bf16.bf16.f32 "
        "{%0,%1,%2,%3}, {%4,%5,%6,%7}, {%8,%9}, {%0,%1,%2,%3};"
        : "+f"(d[0]), "+f"(d[1]), "+f"(d[2]), "+f"(d[3])
        : "r"(a0), "r"(a1), "r"(a2), "r"(a3), "r"(b0), "r"(b1));
}

__global__ __launch_bounds__(NTHREADS) void afm_kernel(
    const int* __restrict__ x_raw,            // [B,24] int32 OR int64 (auto-detect)
    const float* __restrict__ embed_table,    // [V,16]
    const float* __restrict__ linear_table,   // [V,1]
    const float* __restrict__ linear_bias,    // [1]
    const float* __restrict__ attn_W,         // [16,32]
    const float* __restrict__ attn_b,         // [32]
    const float* __restrict__ proj_w,         // [32,1]
    const float* __restrict__ proj_b,         // [1]
    const float* __restrict__ fc_w,           // [16,1]
    const float* __restrict__ fc_b,           // [1]
    float* __restrict__ out)                  // [B,1]
{
    __shared__ __align__(16) float s_emb[NS][NF][EPAD];          // 3456 B
    __shared__ __align__(16) __nv_bfloat16 s_Wt[NWT * NE];       // W' transposed [n][k], 1280 B
    __shared__ __align__(4)  uchar2 s_pairs[PPS];                // (r,c) per padded pair
    __shared__ float s_score[ROWS];
    __shared__ float s_gv[ROWS];
    __shared__ float s_bias[NA];
    __shared__ float s_pw[NA];
    __shared__ int   s_gid[NS][NF];
    __shared__ float s_lin[NS][NF];
    __shared__ float s_scal[2];                                  // proj_b, fc_b+linear_bias
    __shared__ float s_red[3][NS][NWARP];
    __shared__ float s_smax[NS];

    const int tid  = threadIdx.x;
    const int wid  = tid >> 5;
    const int lane = tid & 31;
    const int tig  = lane & 3;        // thread in quad
    const int grp  = lane >> 2;       // quad id = row-in-tile
    const long long b0 = (long long)blockIdx.x * NS;

    // dtype probe: int64 values < 50000 have zero high words at odd positions.
    const bool is64 = (x_raw[1] == 0) & (x_raw[3] == 0) & (x_raw[5] == 0) & (x_raw[7] == 0);

    // ---- stage indices + linear terms ----
    if (tid < NS * NF) {
        int s = tid / NF;
        int f = tid - s * NF;
        long long flat = (b0 + s) * NF + f;
        int xv = is64 ? x_raw[flat * 2] : x_raw[flat];
        int gid = xv + f * 50000;
        s_gid[s][f] = gid;
        s_lin[s][f] = linear_table[gid];
    }
    // W' transposed to [n][k] bf16 (k contiguous): n<32 -> attn_W[k][n]; n==32 -> fc_w; else 0
    for (int t = tid; t < NWT * NE; t += NTHREADS) {
        int n = t / NE, k = t - n * NE;
        float v = (n < NA) ? attn_W[k * NA + n] : ((n == NA) ? fc_w[k] : 0.f);
        s_Wt[n * NE + k] = __float2bfloat16(v);
    }
    // pair LUT (padded entries harmless)
    for (int p = tid; p < PPS; p += NTHREADS) {
        int r = 0, c = 1;
        if (p < NP) {
            int pp = p, base = 0;
            while (pp >= base + (NF - 1 - r)) { base += NF - 1 - r; r++; }
            c = r + 1 + (pp - base);
        }
        s_pairs[p] = make_uchar2((unsigned char)r, (unsigned char)c);
    }
    if (tid < NA) {
        s_bias[tid] = attn_b[tid];
        s_pw[tid]   = proj_w[tid];
    }
    if (tid == 0) {
        s_scal[0] = proj_b[0];
        s_scal[1] = fc_b[0] + linear_bias[0];
    }
    __syncthreads();

    // ---- gather embeddings as float2 (48 rows x 8 chunks) ----
    for (int t = tid; t < NS * NF * 8; t += NTHREADS) {
        int s = t / (NF * 8);
        int rem = t - s * (NF * 8);
        int f = rem >> 3, q = rem & 7;
        const float2* src = (const float2*)embed_table;
        *(float2*)&s_emb[s][f][q * 2] = src[(long long)s_gid[s][f] * 8 + q];
    }
    __syncthreads();

    // ---- preload B fragments (W', 5 n-tiles) + bias/proj for this lane's cols ----
    uint32_t bfr[5][2];
    {
        const uint32_t* wt32 = (const uint32_t*)s_Wt;
        #pragma unroll
        for (int t = 0; t < 5; t++) {
            int n = 8 * t + grp;
            bfr[t][0] = wt32[(n * NE + tig * 2) >> 1];       // k = tig*2, tig*2+1
            bfr[t][1] = wt32[(n * NE + tig * 2 + 8) >> 1];   // k = tig*2+8, +9
        }
    }
    float bias8[8], pw8[8];
    #pragma unroll
    for (int t = 0; t < 4; t++) {
        int c = 8 * t + tig * 2;
        bias8[2*t]   = s_bias[c];
        bias8[2*t+1] = s_bias[c + 1];
        pw8[2*t]     = s_pw[c];
        pw8[2*t+1]   = s_pw[c + 1];
    }

    // ---- per-warp: 9 M-tiles ----
    const int c0 = tig * 2;
    for (int i = 0; i < TPW; i++) {
        int m = wid * TPW + i;
        int smp = (m >= NTILES / 2);
        int pb = (m - smp * (NTILES / 2)) * 16;
        const float* eb = &s_emb[smp][0][0];

        // A fragments: rows pA = pb+grp (a0,a2), pB = pA+8 (a1,a3); k cols c0..c0+1, c0+8..c0+9
        uchar2 qa = s_pairs[pb + grp];
        uchar2 qb = s_pairs[pb + grp + 8];
        const float* ra = eb + (int)qa.x * EPAD;
        const float* ca = eb + (int)qa.y * EPAD;
        const float* rb = eb + (int)qb.x * EPAD;
        const float* cb = eb + (int)qb.y * EPAD;
        float2 raL = *(const float2*)(ra + c0),     caL = *(const float2*)(ca + c0);
        float2 raH = *(const float2*)(ra + c0 + 8), caH = *(const float2*)(ca + c0 + 8);
        float2 rbL = *(const float2*)(rb + c0),     cbL = *(const float2*)(cb + c0);
        float2 rbH = *(const float2*)(rb + c0 + 8), cbH = *(const float2*)(cb + c0 + 8);
        uint32_t a0 = bf16x2_of(raL.x * caL.x, raL.y * caL.y);
        uint32_t a1 = bf16x2_of(rbL.x * cbL.x, rbL.y * cbL.y);
        uint32_t a2 = bf16x2_of(raH.x * caH.x, raH.y * caH.y);
        uint32_t a3 = bf16x2_of(rbH.x * cbH.x, rbH.y * cbH.y);

        float d[5][4];
        #pragma unroll
        for (int t = 0; t < 5; t++) {
            d[t][0] = d[t][1] = d[t][2] = d[t][3] = 0.f;
            mma_bf16(d[t], a0, a1, a2, a3, bfr[t][0], bfr[t][1]);
        }

        // epilogue: relu(d + bias) . projw per row; g from col 32 (tile 4, tig==0, d[4][0]/d[4][2])
        float pa = 0.f, pbv = 0.f;
        #pragma unroll
        for (int t = 0; t < 4; t++) {
            pa  = fmaf(fmaxf(d[t][0] + bias8[2*t],     0.f), pw8[2*t],     pa);
            pa  = fmaf(fmaxf(d[t][1] + bias8[2*t + 1], 0.f), pw8[2*t + 1], pa);
            pbv = fmaf(fmaxf(d[t][2] + bias8[2*t],     0.f), pw8[2*t],     pbv);
            pbv = fmaf(fmaxf(d[t][3] + bias8[2*t + 1], 0.f), pw8[2*t + 1], pbv);
        }
        float ga = (tig == 0) ? d[4][0] : 0.f;
        float gb = (tig == 0) ? d[4][2] : 0.f;

        // quad reduction (lanes 4q..4q+3)
        pa  += __shfl_xor_sync(0xffffffffu, pa, 1);  pa  += __shfl_xor_sync(0xffffffffu, pa, 2);
        pbv += __shfl_xor_sync(0xffffffffu, pbv, 1); pbv += __shfl_xor_sync(0xffffffffu, pbv, 2);
        ga  += __shfl_xor_sync(0xffffffffu, ga, 1);  ga  += __shfl_xor_sync(0xffffffffu, ga, 2);
        gb  += __shfl_xor_sync(0xffffffffu, gb, 1);  gb  += __shfl_xor_sync(0xffffffffu, gb, 2);

        if (tig == 0) {
            int rbase = m * 16 + grp;
            s_score[rbase]     = pa  + s_scal[0];
            s_score[rbase + 8] = pbv + s_scal[0];
            s_gv[rbase]     = ga;
            s_gv[rbase + 8] = gb;
        }
    }
    __syncthreads();

    // ---- block softmax over 276 pairs, both samples ----
    float mx0 = -1e30f, mx1 = -1e30f;
    for (int p = tid; p < NP; p += NTHREADS) {
        mx0 = fmaxf(mx0, s_score[p]);
        mx1 = fmaxf(mx1, s_score[PPS + p]);
    }
    #pragma unroll
    for (int o = 16; o > 0; o >>= 1) {
        mx0 = fmaxf(mx0, __shfl_xor_sync(0xffffffffu, mx0, o));
        mx1 = fmaxf(mx1, __shfl_xor_sync(0xffffffffu, mx1, o));
    }
    if (lane == 0) { s_red[0][0][wid] = mx0; s_red[0][1][wid] = mx1; }
    __syncthreads();
    if (tid == 0) {
        float a = s_red[0][0][0], b = s_red[0][1][0];
        #pragma unroll
        for (int w = 1; w < NWARP; w++) {
            a = fmaxf(a, s_red[0][0][w]);
            b = fmaxf(b, s_red[0][1][w]);
        }
        s_smax[0] = a; s_smax[1] = b;
    }
    __syncthreads();

    const float sm0 = s_smax[0], sm1 = s_smax[1];
    float se0 = 0.f, sg0 = 0.f, se1 = 0.f, sg1 = 0.f;
    for (int p = tid; p < NP; p += NTHREADS) {
        float e0 = __expf(s_score[p] - sm0);
        float e1 = __expf(s_score[PPS + p] - sm1);
        se0 += e0; sg0 += e0 * s_gv[p];
        se1 += e1; sg1 += e1 * s_gv[PPS + p];
    }
    #pragma unroll
    for (int o = 16; o > 0; o >>= 1) {
        se0 += __shfl_xor_sync(0xffffffffu, se0, o);
        sg0 += __shfl_xor_sync(0xffffffffu, sg0, o);
        se1 += __shfl_xor_sync(0xffffffffu, se1, o);
        sg1 += __shfl_xor_sync(0xffffffffu, sg1, o);
    }
    if (lane == 0) {
        s_red[1][0][wid] = se0; s_red[2][0][wid] = sg0;
        s_red[1][1][wid] = se1; s_red[2][1][wid] = sg1;
    }
    __syncthreads();

    if (tid < NS) {
        int s = tid;
        float tse = 0.f, tsg = 0.f;
        #pragma unroll
        for (int w = 0; w < NWARP; w++) { tse += s_red[1][s][w]; tsg += s_red[2][s][w]; }
        float lin = 0.f;
        #pragma unroll
        for (int f = 0; f < NF; f++) lin += s_lin[s][f];
        out[b0 + s] = lin + s_scal[1] + tsg / tse;
    }
}

extern "C" void kernel_launch(void* const* d_in, const int* in_sizes, int n_in,
                              void* d_out, int out_size) {
    const int* x              = (const int*)d_in[0];
    const float* embed_table  = (const float*)d_in[1];
    const float* linear_table = (const float*)d_in[2];
    const float* linear_bias  = (const float*)d_in[3];
    const float* attn_W       = (const float*)d_in[4];
    const float* attn_b       = (const float*)d_in[5];
    const float* proj_w       = (const float*)d_in[6];
    const float* proj_b       = (const float*)d_in[7];
    const float* fc_w         = (const float*)d_in[8];
    const float* fc_b         = (const float*)d_in[9];
    float* out = (float*)d_out;

    int B = out_size;                 // one output per sample
    int nblocks = (B + NS - 1) / NS;  // 16384 -> 8192
    afm_kernel<<<nblocks, NTHREADS>>>(x, embed_table, linear_table, linear_bias,
                                      attn_W, attn_b, proj_w, proj_b, fc_w, fc_b, out);
}